// round 17
// baseline (speedup 1.0000x reference)
#include <cuda_runtime.h>
#include <cuda_bf16.h>
#include <cstdint>

#define DD 128
#define MAXN 100000
#define MAXN_PAD 100032      // 1563 * 64
#define MAXE 640000

// ---------------- scratch (no allocations allowed) ----------------
__device__ float g_conv[(size_t)MAXN * DD];
__device__ float g_sdeg[MAXN];
__device__ float g_rdeg[MAXN];
__device__ float g_an  [DD];
__device__ float g_gvec[DD];
// W terms in [n][k] layout with pitch 136 elems (272 B): W1h, W1l, W2h, W2l
#define WPITCH 136
#define WTERM  (128 * WPITCH)          // 17408 elems = 34816 B
__device__ __nv_bfloat16 g_wstage[4 * WTERM];
// pre-converted A (bf16 hi/lo), contiguous [MAXN_PAD][128]
__device__ __nv_bfloat16 g_ahi[(size_t)MAXN_PAD * DD];
__device__ __nv_bfloat16 g_alo[(size_t)MAXN_PAD * DD];

// ---------------- PTX helpers ----------------
__device__ __forceinline__ uint32_t smem_u32(const void* p) {
    uint32_t a;
    asm("{ .reg .u64 t; cvta.to.shared.u64 t, %1; cvt.u32.u64 %0, t; }" : "=r"(a) : "l"(p));
    return a;
}
__device__ __forceinline__ void ldsm4(uint32_t* r, uint32_t addr) {
    asm volatile("ldmatrix.sync.aligned.m8n8.x4.shared.b16 {%0,%1,%2,%3}, [%4];"
                 : "=r"(r[0]), "=r"(r[1]), "=r"(r[2]), "=r"(r[3]) : "r"(addr));
}
__device__ __forceinline__ void mma16816(float* c, const uint32_t* a, uint32_t b0, uint32_t b1) {
    asm volatile("mma.sync.aligned.m16n8k16.row.col.f32.bf16.bf16.f32 "
                 "{%0,%1,%2,%3}, {%4,%5,%6,%7}, {%8,%9}, {%0,%1,%2,%3};"
                 : "+f"(c[0]), "+f"(c[1]), "+f"(c[2]), "+f"(c[3])
                 : "r"(a[0]), "r"(a[1]), "r"(a[2]), "r"(a[3]), "r"(b0), "r"(b1));
}
__device__ __forceinline__ void cp16(uint32_t dst, const void* src) {
    asm volatile("cp.async.cg.shared.global [%0], [%1], 16;" :: "r"(dst), "l"(src));
}
#define CP_COMMIT() asm volatile("cp.async.commit_group;" ::: "memory")
#define CP_WAIT0()  asm volatile("cp.async.wait_group 0;" ::: "memory")

// ---------------- kernel 1: zero small scratch ----------------
__global__ void k_zero(int n) {
    int tid = blockIdx.x * blockDim.x + threadIdx.x;
    int stride = gridDim.x * blockDim.x;
    for (int i = tid; i < n; i += stride) { g_sdeg[i] = 0.f; g_rdeg[i] = 0.f; }
    if (tid < DD) g_an[tid] = 0.f;
}

// ---------------- kernel 2: degrees + fused gvec (last block) ----------------
__global__ void k_degv(const int* __restrict__ snd, const int* __restrict__ rcv, int e,
                       const float* __restrict__ g, const float* __restrict__ W3,
                       const float* __restrict__ b3) {
    if (blockIdx.x == gridDim.x - 1) {
        __shared__ float part[2][DD];
        int c = threadIdx.x & (DD - 1);
        int p = threadIdx.x >> 7;
        float s = 0.f;
        int kbeg = p * 64;
#pragma unroll
        for (int k = 0; k < 64; k += 4) {
            float s0 = g[kbeg + k + 0] * W3[(kbeg + k + 0) * DD + c];
            float s1 = g[kbeg + k + 1] * W3[(kbeg + k + 1) * DD + c];
            float s2 = g[kbeg + k + 2] * W3[(kbeg + k + 2) * DD + c];
            float s3 = g[kbeg + k + 3] * W3[(kbeg + k + 3) * DD + c];
            s += (s0 + s1) + (s2 + s3);
        }
        part[p][c] = s;
        __syncthreads();
        if (p == 0) g_gvec[c] = part[0][c] + part[1][c] + b3[c];
        return;
    }
    int i = blockIdx.x * blockDim.x + threadIdx.x;
    if (i < e) {
        atomicAdd(&g_sdeg[snd[i]], 1.0f);
        atomicAdd(&g_rdeg[rcv[i]], 1.0f);
    }
}

// ---------------- kernel 2b: W -> bf16 hi/lo, [n][k] pitch-136 ----------------
__global__ void k_wconv(const float* __restrict__ W1, const float* __restrict__ W2) {
    int idx = blockIdx.x * blockDim.x + threadIdx.x;
    int mat = idx >> 14;
    int nn  = (idx >> 7) & 127;
    int k   = idx & 127;
    float w = (mat ? W2 : W1)[k * DD + nn];
    __nv_bfloat16 hi = __float2bfloat16(w);
    __nv_bfloat16 lo = __float2bfloat16(w - __bfloat162float(hi));
    int off = nn * WPITCH + k;
    g_wstage[(mat * 2 + 0) * WTERM + off] = hi;
    g_wstage[(mat * 2 + 1) * WTERM + off] = lo;
}

// ---------------- kernel 2c: A -> bf16 hi/lo (padded, contiguous) ----------------
__global__ void k_aconv(const float* __restrict__ nodes, int n) {
    long i4 = (long)blockIdx.x * blockDim.x + threadIdx.x;
    long tot = (long)MAXN_PAD * DD / 4;
    long stride = (long)gridDim.x * blockDim.x;
    for (; i4 < tot; i4 += stride) {
        long row = i4 >> 5;
        float4 v = make_float4(0.f, 0.f, 0.f, 0.f);
        if (row < n) v = ((const float4*)nodes)[i4];
        __nv_bfloat16 hx = __float2bfloat16(v.x), hy = __float2bfloat16(v.y);
        __nv_bfloat16 hz = __float2bfloat16(v.z), hw = __float2bfloat16(v.w);
        __nv_bfloat16 lx = __float2bfloat16(v.x - __bfloat162float(hx));
        __nv_bfloat16 ly = __float2bfloat16(v.y - __bfloat162float(hy));
        __nv_bfloat16 lz = __float2bfloat16(v.z - __bfloat162float(hz));
        __nv_bfloat16 lw = __float2bfloat16(v.w - __bfloat162float(hw));
        uint2 hp, lp;
        hp.x = ((uint32_t)__bfloat16_as_ushort(hy) << 16) | __bfloat16_as_ushort(hx);
        hp.y = ((uint32_t)__bfloat16_as_ushort(hw) << 16) | __bfloat16_as_ushort(hz);
        lp.x = ((uint32_t)__bfloat16_as_ushort(ly) << 16) | __bfloat16_as_ushort(lx);
        lp.y = ((uint32_t)__bfloat16_as_ushort(lw) << 16) | __bfloat16_as_ushort(lz);
        ((uint2*)g_ahi)[i4] = hp;
        ((uint2*)g_alo)[i4] = lp;
    }
}

// ---------------- kernel 3: split-bf16 dual GEMM, 256 thr, 2 CTA/SM, n-split ----
// smem per CTA: b1[512] | b2[512] | A (Ahi+Alo, 64r x 272B each) | W-half (4 x 17408)
#define SM_B1   0
#define SM_B2   512
#define SM_A    1024
#define ABUF    34816
#define SM_W    (SM_A + ABUF)          // 35840
#define WHALF   17408                  // 64 rows x 272 B per term
#define SM_TOT  (SM_W + 4 * WHALF)     // 105472 B

__device__ __forceinline__ void load_tile_a(uint32_t sb, int tile, int tid) {
    long row0 = (long)tile * 64;
#pragma unroll
    for (int j = 0; j < 8; j++) {
        int c = tid + j * 256;                 // 2048 chunks of 16 B
        int term = c >> 10;
        int rr   = (c >> 4) & 63;
        int col  = c & 15;
        uint32_t dst = sb + SM_A + (uint32_t)term * 17408 + (uint32_t)rr * 272 + (uint32_t)(col << 4);
        const char* srcb = (const char*)(term ? g_alo : g_ahi)
                         + ((row0 + rr) << 8) + (col << 4);
        cp16(dst, srcb);
    }
}

__global__ void __launch_bounds__(256, 2) k_mm(
    const float* __restrict__ b1, const float* __restrict__ b2,
    float* __restrict__ outH, int n)
{
    extern __shared__ char smem[];
    uint32_t sb = smem_u32(smem);
    int tid = threadIdx.x;
    int warp = tid >> 5, lane = tid & 31;
    int wn = warp & 3;                  // 16-col group within this CTA's 64-col half
    int wm = warp >> 2;                 // 0/1: rows 0-31 / 32-63
    int ch = blockIdx.x & 1;            // column half: 0 -> cols 0-63, 1 -> 64-127
    int ntiles = (n + 63) >> 6;

    // stage this CTA's W half-terms (rows [ch*64, ch*64+64) of each term) + biases
    {
        const char* wsrc = (const char*)g_wstage;
        for (int i = tid; i < 4352; i += 256) {          // 4 terms x 1088 chunks
            int t = i >> 10;          // careful: 1088 not pow2 — use div
            t = i / 1088;
            int j = i - t * 1088;
            *(float4*)(smem + SM_W + t * WHALF + j * 16) =
                *(const float4*)(wsrc + t * 34816 + ch * WHALF + j * 16);
        }
        if (tid < 32) {
            ((float4*)(smem + SM_B1))[tid] = ((const float4*)b1)[tid];
            ((float4*)(smem + SM_B2))[tid] = ((const float4*)b2)[tid];
        }
    }

    const float* b1s = (const float*)(smem + SM_B1);
    const float* b2s = (const float*)(smem + SM_B2);

    uint32_t lrow = lane & 15;
    uint32_t khb  = (lane >> 4) << 4;
    uint32_t aoff = lrow * 272 + khb + (uint32_t)wm * (32 * 272);
    uint32_t boff = ((uint32_t)wn * 16 + lrow) * 272 + khb;

    int qrow = lane >> 2;
    int qcol = (lane & 3) << 1;

    int tile0  = blockIdx.x >> 1;
    int stride = gridDim.x >> 1;

    if (tile0 < ntiles) load_tile_a(sb, tile0, tid);
    CP_COMMIT();
    __syncthreads();    // W staging complete (and orders cp.async issue)

    for (int tile = tile0; tile < ntiles; tile += stride) {
        CP_WAIT0();
        __syncthreads();    // A tile ready for all warps

        uint32_t abase = sb + SM_A + aoff;

        float acc[2][2][2][4];
#pragma unroll
        for (int m = 0; m < 2; m++)
#pragma unroll
            for (int nt = 0; nt < 2; nt++)
#pragma unroll
                for (int mt = 0; mt < 2; mt++)
#pragma unroll
                    for (int c = 0; c < 4; c++) acc[m][nt][mt][c] = 0.f;

#pragma unroll
        for (int ks = 0; ks < 8; ks++) {
            uint32_t kb = (uint32_t)ks * 32;
            uint32_t bf[4][4];
#pragma unroll
            for (int t = 0; t < 4; t++)
                ldsm4(bf[t], sb + SM_W + (uint32_t)t * WHALF + boff + kb);
#pragma unroll
            for (int m = 0; m < 2; m++) {
                uint32_t ah[4], al[4];
                uint32_t ab = abase + (uint32_t)m * (16 * 272) + kb;
                ldsm4(ah, ab);
                ldsm4(al, ab + 17408);
                mma16816(acc[m][0][0], ah, bf[0][0], bf[0][2]);
                mma16816(acc[m][1][0], ah, bf[0][1], bf[0][3]);
                mma16816(acc[m][0][0], ah, bf[1][0], bf[1][2]);
                mma16816(acc[m][1][0], ah, bf[1][1], bf[1][3]);
                mma16816(acc[m][0][0], al, bf[0][0], bf[0][2]);
                mma16816(acc[m][1][0], al, bf[0][1], bf[0][3]);
                mma16816(acc[m][0][1], ah, bf[2][0], bf[2][2]);
                mma16816(acc[m][1][1], ah, bf[2][1], bf[2][3]);
                mma16816(acc[m][0][1], ah, bf[3][0], bf[3][2]);
                mma16816(acc[m][1][1], ah, bf[3][1], bf[3][3]);
                mma16816(acc[m][0][1], al, bf[2][0], bf[2][2]);
                mma16816(acc[m][1][1], al, bf[2][1], bf[2][3]);
            }
        }
        __syncthreads();    // all warps done reading A smem

        // prefetch next tile while epilogue stores run
        int nexttile = tile + stride;
        if (nexttile < ntiles) load_tile_a(sb, nexttile, tid);
        CP_COMMIT();

        int row0 = tile << 6;
#pragma unroll
        for (int m = 0; m < 2; m++) {
#pragma unroll
            for (int h = 0; h < 2; h++) {
                int grow = row0 + wm * 32 + m * 16 + qrow + h * 8;
                if (grow >= n) continue;
                float f = rsqrtf(fmaxf(g_sdeg[grow], 1.0f));
                long gb = (long)grow * DD;
#pragma unroll
                for (int nt = 0; nt < 2; nt++) {
                    int col = ch * 64 + wn * 16 + nt * 8 + qcol;
                    float2 o1, o2;
                    o1.x = acc[m][nt][0][2 * h + 0] + b1s[col + 0];
                    o1.y = acc[m][nt][0][2 * h + 1] + b1s[col + 1];
                    o2.x = (acc[m][nt][1][2 * h + 0] + b2s[col + 0]) * f;
                    o2.y = (acc[m][nt][1][2 * h + 1] + b2s[col + 1]) * f;
                    *(float2*)(outH + gb + col)   = o1;
                    *(float2*)(g_conv + gb + col) = o2;
                }
            }
        }
    }
}

// ---------------- kernel 4: edge scatter, fused recv-norm, into out ----------------
__global__ void k_scatter(const int* __restrict__ snd, const int* __restrict__ rcv,
                          float* __restrict__ out, int e) {
    int gw = (blockIdx.x * blockDim.x + threadIdx.x) >> 5;
    int lane = threadIdx.x & 31;
    if (gw >= e) return;
    int s = snd[gw];
    int r = rcv[gw];
    float rs = rsqrtf(fmaxf(g_rdeg[r], 1.0f));
    float4 v = ((const float4*)(g_conv + (long)s * DD))[lane];
    v.x *= rs; v.y *= rs; v.z *= rs; v.w *= rs;
    atomicAdd(((float4*)(out + (long)r * DD)) + lane, v);
}

// ---------------- kernel 5: finalize h, accumulate an ----------------
#define RPB 64
__global__ void k_final(const float* __restrict__ nodes, float* __restrict__ out, int n) {
    __shared__ float red[256];
    int c    = threadIdx.x & (DD - 1);
    int half = threadIdx.x >> 7;
    int rs0  = blockIdx.x * RPB;
    int rs1  = min(rs0 + RPB, n);
    float gv = g_gvec[c];
    float local = 0.f;
    for (int r = rs0 + half; r < rs1; r += 2) {
        long idx = (long)r * DD + c;
        float v = out[idx] + gv;
        v = fmaxf(v, 0.f) + nodes[idx];
        out[idx] = v;
        local += v;
    }
    red[threadIdx.x] = local;
    __syncthreads();
    if (half == 0) atomicAdd(&g_an[c], red[c] + red[c + DD]);
}

// ---------------- kernel 6: global update ----------------
__global__ void k_gout(const float* __restrict__ g, const float* __restrict__ Wg,
                       const float* __restrict__ bg, float* __restrict__ out, long off) {
    __shared__ float part[4][DD];
    int c = threadIdx.x & (DD - 1);
    int p = threadIdx.x >> 7;
    float s = 0.f;
    int kbeg = p * 64;
#pragma unroll
    for (int k = 0; k < 64; k += 4) {
        int kk = kbeg + k;
        float x0 = (kk + 0 < DD) ? g_an[kk + 0] : g[kk + 0 - DD];
        float x1 = (kk + 1 < DD) ? g_an[kk + 1] : g[kk + 1 - DD];
        float x2 = (kk + 2 < DD) ? g_an[kk + 2] : g[kk + 2 - DD];
        float x3 = (kk + 3 < DD) ? g_an[kk + 3] : g[kk + 3 - DD];
        s += (x0 * Wg[(kk + 0) * DD + c] + x1 * Wg[(kk + 1) * DD + c])
           + (x2 * Wg[(kk + 2) * DD + c] + x3 * Wg[(kk + 3) * DD + c]);
    }
    part[p][c] = s;
    __syncthreads();
    if (p == 0) {
        float v = part[0][c] + part[1][c] + part[2][c] + part[3][c] + bg[c];
        out[off + c] = g[c] + fmaxf(v, 0.f);
    }
}

// ---------------- launch ----------------
extern "C" void kernel_launch(void* const* d_in, const int* in_sizes, int n_in,
                              void* d_out, int out_size) {
    const float* nodes    = (const float*)d_in[0];
    const float* globals_ = (const float*)d_in[1];
    const int*   senders  = (const int*)d_in[2];
    const int*   receivers= (const int*)d_in[3];
    const float* W1w = (const float*)d_in[4];
    const float* W1b = (const float*)d_in[5];
    const float* W2w = (const float*)d_in[6];
    const float* W2b = (const float*)d_in[7];
    const float* W3w = (const float*)d_in[8];
    const float* W3b = (const float*)d_in[9];
    const float* Wgw = (const float*)d_in[10];
    const float* Wgb = (const float*)d_in[11];
    float* out = (float*)d_out;

    int n = in_sizes[0] / DD;
    int e = in_sizes[2];

    cudaFuncSetAttribute(k_mm, cudaFuncAttributeMaxDynamicSharedMemorySize, SM_TOT);

    k_zero<<<128, 256>>>(n);
    k_degv<<<(e + 255) / 256 + 1, 256>>>(senders, receivers, e, globals_, W3w, W3b);
    k_wconv<<<256, 256>>>(W1w, W2w);
    k_aconv<<<2048, 256>>>(nodes, n);
    k_mm<<<296, 256, SM_TOT>>>(W1b, W2b, out, n);
    k_scatter<<<(e + 7) / 8, 256>>>(senders, receivers, out, e);
    k_final<<<(n + RPB - 1) / RPB, 256>>>(nodes, out, n);
    k_gout<<<1, 512>>>(globals_, Wgw, Wgb, out, (long)n * DD);
}